// round 13
// baseline (speedup 1.0000x reference)
#include <cuda_runtime.h>
#include <cuda_bf16.h>

// Piecewise-linear log-sigmoid approximation (table interp), GB300 sm_103a.
// vals: [64,2048,2048] fp32, x/y: 65-entry uniform tables.
//   x[i] = -10 + i*0.3125 (step 5/16, exact in fp32)
//   idx  = clamp((int)(v*3.2 + 32), 0, 63)
//   out  = v                          if v <  x[0]
//          0                          if v >= x[64]
//          y[i] + (v - x[i])*slope[i] otherwise
//
// FINAL CHAMPION (5x reconfirmed: 306.27-307.65us wall, 6929-6954 GB/s):
// 512 threads x V4=4 front-batched LDG.128 (MLP_p1=4), float2 (y_lo, slope)
// LDS table + analytic x_lo, exact-tile int32 addressing, flat launch.
//
// Convergence evidence (12 rounds, predict->verify each):
//   vectorization:     scalar->float4 403->308us (the structural win)
//   MLP_p1 {1,2,4,8}:  {66-78, 86.9, 87.6, 79}% DRAM  (4 = optimum)
//   table layout:      float2 vs 32x lane-replicated -> neutral
//   persistence:       grid-stride -> -9% (serializes the stream)
//   cache hints:       __ldcs/__stcs -> neutral
//   block size:        256 vs 512 -> neutral
//   store scheduling:  burst vs interleaved -> neutral
// Traffic is the algorithmic minimum (8 B/element, single pass). Combined
// LTS traffic (~14.2 TB/s) and HBM r+w (~6.95 TB/s) sit on the measured
// path-independent chip streaming cap — a TMA-store path cannot exceed it
// (B300: LDG.cv ≡ TMA at the LTS cap). 87.6% of spec = achieved ceiling
// for a balanced 1:1 read/write stream.

#define NBP 65
#define NSEG 64
#define THREADS 512
#define V4_PER_THREAD 4                       // float4s per thread (MLP_p1 = 4)
#define TILE_F4 (THREADS * V4_PER_THREAD)     // 2048 float4s per block

__global__ __launch_bounds__(THREADS)
void logsig_pwl_kernel(const float4* __restrict__ in4,
                       const float*  __restrict__ xt,
                       const float*  __restrict__ yt,
                       float4* __restrict__ out4)
{
    __shared__ float2 s_seg[NSEG];      // (y_lo, slope) per segment
    __shared__ float  s_bounds[2];

    const int tid = threadIdx.x;
    if (tid < NSEG) {
        float xl = xt[tid], xh = xt[tid + 1];
        float yl = yt[tid], yh = yt[tid + 1];
        s_seg[tid] = make_float2(yl, (yh - yl) / (xh - xl));
    }
    if (tid == 0) { s_bounds[0] = xt[0]; s_bounds[1] = xt[NBP - 1]; }
    __syncthreads();

    const float x_lo_bound = s_bounds[0];   // -10
    const float x_hi_bound = s_bounds[1];   // +10
    const float INV_H = 3.2f;
    const float OFFS  = 32.0f;
    const float H     = 0.3125f;            // 5/16, exact
    const float X0    = -10.0f;

    // Exact-tile addressing: every access in range by construction.
    // Max index = 67,108,863 < 2^31 -> int32 math only.
    unsigned base = blockIdx.x * TILE_F4 + tid;

    // Front-batched loads -> 4 LDG.128 in flight per thread (MLP_p1 = 4).
    float4 v[V4_PER_THREAD];
    #pragma unroll
    for (int j = 0; j < V4_PER_THREAD; j++)
        v[j] = in4[base + j * THREADS];

    #pragma unroll
    for (int j = 0; j < V4_PER_THREAD; j++) {
        float vv[4] = {v[j].x, v[j].y, v[j].z, v[j].w};
        float r[4];
        #pragma unroll
        for (int k = 0; k < 4; k++) {
            float val = vv[k];
            int idx = (int)fmaf(val, INV_H, OFFS);
            idx = max(0, min(idx, NSEG - 1));
            float2 seg = s_seg[idx];                 // one LDS.64
            float x_lo = fmaf((float)idx, H, X0);    // exact, matches xt[idx]
            float interp = fmaf(val - x_lo, seg.y, seg.x);
            r[k] = (val <  x_lo_bound) ? val
                 : (val >= x_hi_bound) ? 0.0f
                 : interp;
        }
        float4 o; o.x = r[0]; o.y = r[1]; o.z = r[2]; o.w = r[3];
        out4[base + j * THREADS] = o;
    }
}

// Tail kernel: scalar, handles [start, n) elements (not hit for this shape,
// but keeps the kernel correct for any n).
__global__ void logsig_pwl_tail(const float* __restrict__ vals,
                                const float* __restrict__ xt,
                                const float* __restrict__ yt,
                                float* __restrict__ out,
                                long long start, long long n)
{
    long long i = start + (long long)blockIdx.x * blockDim.x + threadIdx.x;
    if (i >= n) return;
    float x0 = xt[0];
    float xK = xt[NBP - 1];
    float val = vals[i];
    int idx = (int)fmaf(val, 3.2f, 32.0f);
    idx = max(0, min(idx, NSEG - 1));
    float x_lo = xt[idx];
    float y_lo = yt[idx];
    float slope = (yt[idx + 1] - y_lo) / (xt[idx + 1] - x_lo);
    float interp = fmaf(val - x_lo, slope, y_lo);
    out[i] = (val < x0) ? val : (val >= xK) ? 0.0f : interp;
}

extern "C" void kernel_launch(void* const* d_in, const int* in_sizes, int n_in,
                              void* d_out, int out_size)
{
    const float* vals = (const float*)d_in[0];
    const float* xt   = (const float*)d_in[1];
    const float* yt   = (const float*)d_in[2];
    float* out        = (float*)d_out;

    long long n  = (long long)in_sizes[0];
    long long n4 = n / 4;

    long long fullBlocks = n4 / TILE_F4;
    long long covered    = fullBlocks * TILE_F4 * 4;   // elements by main kernel

    if (fullBlocks > 0) {
        logsig_pwl_kernel<<<(unsigned)fullBlocks, THREADS>>>(
            (const float4*)vals, xt, yt, (float4*)out);
    }
    if (covered < n) {
        long long rem = n - covered;
        int tblocks = (int)((rem + 255) / 256);
        logsig_pwl_tail<<<tblocks, 256>>>(vals, xt, yt, out, covered, n);
    }
}

// round 14
// speedup vs baseline: 1.0031x; 1.0031x over previous
#include <cuda_runtime.h>
#include <cuda_bf16.h>

// Piecewise-linear log-sigmoid approximation (table interp), GB300 sm_103a.
// vals: [64,2048,2048] fp32, x/y: 65-entry uniform tables.
//   x[i] = -10 + i*0.3125 (step 5/16, exact in fp32)
//   idx  = clamp((int)(v*3.2 + 32), 0, 63)
//   out  = v                          if v <  x[0]
//          0                          if v >= x[64]
//          y[i] + (v - x[i])*slope[i] otherwise
//
// FINAL CHAMPION (6x reconfirmed: kernel 301.3-304.7us, 6929-6954 GB/s):
// 512 threads x V4=4 front-batched LDG.128 (MLP_p1=4), float2 (y_lo, slope)
// LDS table + analytic x_lo, exact-tile int32 addressing, flat launch.
//
// Convergence evidence (13 rounds, predict->verify each):
//   vectorization:     scalar->float4 403->308us (the structural win)
//   MLP_p1 {1,2,4,8}:  {66-78, 86.9, 87.6, 79}% DRAM  (4 = optimum)
//   table layout:      float2 vs 32x lane-replicated -> neutral
//   persistence:       grid-stride -> -9% (serializes the stream)
//   cache hints:       __ldcs/__stcs -> neutral
//   block size:        256 vs 512 -> neutral
//   store scheduling:  burst vs interleaved -> neutral
// Traffic is the algorithmic minimum (8 B/element, single pass, no reuse:
// 2 GiB working set >> 126 MB L2). HBM r+w 6.95 TB/s sits on the measured
// path-independent chip streaming cap (B300: LDG.cv ≡ TMA at the LTS cap),
// so no alternative store path can exceed it. 87.6% of spec = achieved
// ceiling for a balanced 1:1 read/write stream.

#define NBP 65
#define NSEG 64
#define THREADS 512
#define V4_PER_THREAD 4                       // float4s per thread (MLP_p1 = 4)
#define TILE_F4 (THREADS * V4_PER_THREAD)     // 2048 float4s per block

__global__ __launch_bounds__(THREADS)
void logsig_pwl_kernel(const float4* __restrict__ in4,
                       const float*  __restrict__ xt,
                       const float*  __restrict__ yt,
                       float4* __restrict__ out4)
{
    __shared__ float2 s_seg[NSEG];      // (y_lo, slope) per segment
    __shared__ float  s_bounds[2];

    const int tid = threadIdx.x;
    if (tid < NSEG) {
        float xl = xt[tid], xh = xt[tid + 1];
        float yl = yt[tid], yh = yt[tid + 1];
        s_seg[tid] = make_float2(yl, (yh - yl) / (xh - xl));
    }
    if (tid == 0) { s_bounds[0] = xt[0]; s_bounds[1] = xt[NBP - 1]; }
    __syncthreads();

    const float x_lo_bound = s_bounds[0];   // -10
    const float x_hi_bound = s_bounds[1];   // +10
    const float INV_H = 3.2f;
    const float OFFS  = 32.0f;
    const float H     = 0.3125f;            // 5/16, exact
    const float X0    = -10.0f;

    // Exact-tile addressing: every access in range by construction.
    // Max index = 67,108,863 < 2^31 -> int32 math only.
    unsigned base = blockIdx.x * TILE_F4 + tid;

    // Front-batched loads -> 4 LDG.128 in flight per thread (MLP_p1 = 4).
    float4 v[V4_PER_THREAD];
    #pragma unroll
    for (int j = 0; j < V4_PER_THREAD; j++)
        v[j] = in4[base + j * THREADS];

    #pragma unroll
    for (int j = 0; j < V4_PER_THREAD; j++) {
        float vv[4] = {v[j].x, v[j].y, v[j].z, v[j].w};
        float r[4];
        #pragma unroll
        for (int k = 0; k < 4; k++) {
            float val = vv[k];
            int idx = (int)fmaf(val, INV_H, OFFS);
            idx = max(0, min(idx, NSEG - 1));
            float2 seg = s_seg[idx];                 // one LDS.64
            float x_lo = fmaf((float)idx, H, X0);    // exact, matches xt[idx]
            float interp = fmaf(val - x_lo, seg.y, seg.x);
            r[k] = (val <  x_lo_bound) ? val
                 : (val >= x_hi_bound) ? 0.0f
                 : interp;
        }
        float4 o; o.x = r[0]; o.y = r[1]; o.z = r[2]; o.w = r[3];
        out4[base + j * THREADS] = o;
    }
}

// Tail kernel: scalar, handles [start, n) elements (not hit for this shape,
// but keeps the kernel correct for any n).
__global__ void logsig_pwl_tail(const float* __restrict__ vals,
                                const float* __restrict__ xt,
                                const float* __restrict__ yt,
                                float* __restrict__ out,
                                long long start, long long n)
{
    long long i = start + (long long)blockIdx.x * blockDim.x + threadIdx.x;
    if (i >= n) return;
    float x0 = xt[0];
    float xK = xt[NBP - 1];
    float val = vals[i];
    int idx = (int)fmaf(val, 3.2f, 32.0f);
    idx = max(0, min(idx, NSEG - 1));
    float x_lo = xt[idx];
    float y_lo = yt[idx];
    float slope = (yt[idx + 1] - y_lo) / (xt[idx + 1] - x_lo);
    float interp = fmaf(val - x_lo, slope, y_lo);
    out[i] = (val < x0) ? val : (val >= xK) ? 0.0f : interp;
}

extern "C" void kernel_launch(void* const* d_in, const int* in_sizes, int n_in,
                              void* d_out, int out_size)
{
    const float* vals = (const float*)d_in[0];
    const float* xt   = (const float*)d_in[1];
    const float* yt   = (const float*)d_in[2];
    float* out        = (float*)d_out;

    long long n  = (long long)in_sizes[0];
    long long n4 = n / 4;

    long long fullBlocks = n4 / TILE_F4;
    long long covered    = fullBlocks * TILE_F4 * 4;   // elements by main kernel

    if (fullBlocks > 0) {
        logsig_pwl_kernel<<<(unsigned)fullBlocks, THREADS>>>(
            (const float4*)vals, xt, yt, (float4*)out);
    }
    if (covered < n) {
        long long rem = n - covered;
        int tblocks = (int)((rem + 255) / 256);
        logsig_pwl_tail<<<tblocks, 256>>>(vals, xt, yt, out, covered, n);
    }
}

// round 15
// speedup vs baseline: 1.0049x; 1.0018x over previous
#include <cuda_runtime.h>
#include <cuda_bf16.h>

// Piecewise-linear log-sigmoid approximation (table interp), GB300 sm_103a.
// vals: [64,2048,2048] fp32, x/y: 65-entry uniform tables.
//   x[i] = -10 + i*0.3125 (step 5/16, exact in fp32)
//   idx  = clamp((int)(v*3.2 + 32), 0, 63)
//   out  = v                          if v <  x[0]
//          0                          if v >= x[64]
//          y[i] + (v - x[i])*slope[i] otherwise
//
// FINAL CHAMPION (7x reconfirmed: kernel 300.9-304.7us, 6929-6958 GB/s):
// 512 threads x V4=4 front-batched LDG.128 (MLP_p1=4), float2 (y_lo, slope)
// LDS table + analytic x_lo, exact-tile int32 addressing, flat launch.
//
// Convergence evidence (14 rounds, predict->verify each):
//   vectorization:     scalar->float4 403->308us (the structural win)
//   MLP_p1 {1,2,4,8}:  {66-78, 86.9, 87.6, 79}% DRAM  (4 = optimum)
//   table layout:      float2 vs 32x lane-replicated -> neutral
//   persistence:       grid-stride -> -9% (serializes the stream)
//   cache hints:       __ldcs/__stcs -> neutral
//   block size:        256 vs 512 -> neutral
//   store scheduling:  burst vs interleaved -> neutral
// Traffic is the algorithmic minimum (8 B/element, single pass, no reuse:
// 2 GiB working set >> 126 MB L2). HBM r+w 6.95 TB/s sits on the measured
// path-independent chip streaming cap (B300: LDG.cv ≡ TMA at the LTS cap),
// so no alternative store path can exceed it. 87.6% of spec = achieved
// ceiling for a balanced 1:1 read/write stream.

#define NBP 65
#define NSEG 64
#define THREADS 512
#define V4_PER_THREAD 4                       // float4s per thread (MLP_p1 = 4)
#define TILE_F4 (THREADS * V4_PER_THREAD)     // 2048 float4s per block

__global__ __launch_bounds__(THREADS)
void logsig_pwl_kernel(const float4* __restrict__ in4,
                       const float*  __restrict__ xt,
                       const float*  __restrict__ yt,
                       float4* __restrict__ out4)
{
    __shared__ float2 s_seg[NSEG];      // (y_lo, slope) per segment
    __shared__ float  s_bounds[2];

    const int tid = threadIdx.x;
    if (tid < NSEG) {
        float xl = xt[tid], xh = xt[tid + 1];
        float yl = yt[tid], yh = yt[tid + 1];
        s_seg[tid] = make_float2(yl, (yh - yl) / (xh - xl));
    }
    if (tid == 0) { s_bounds[0] = xt[0]; s_bounds[1] = xt[NBP - 1]; }
    __syncthreads();

    const float x_lo_bound = s_bounds[0];   // -10
    const float x_hi_bound = s_bounds[1];   // +10
    const float INV_H = 3.2f;
    const float OFFS  = 32.0f;
    const float H     = 0.3125f;            // 5/16, exact
    const float X0    = -10.0f;

    // Exact-tile addressing: every access in range by construction.
    // Max index = 67,108,863 < 2^31 -> int32 math only.
    unsigned base = blockIdx.x * TILE_F4 + tid;

    // Front-batched loads -> 4 LDG.128 in flight per thread (MLP_p1 = 4).
    float4 v[V4_PER_THREAD];
    #pragma unroll
    for (int j = 0; j < V4_PER_THREAD; j++)
        v[j] = in4[base + j * THREADS];

    #pragma unroll
    for (int j = 0; j < V4_PER_THREAD; j++) {
        float vv[4] = {v[j].x, v[j].y, v[j].z, v[j].w};
        float r[4];
        #pragma unroll
        for (int k = 0; k < 4; k++) {
            float val = vv[k];
            int idx = (int)fmaf(val, INV_H, OFFS);
            idx = max(0, min(idx, NSEG - 1));
            float2 seg = s_seg[idx];                 // one LDS.64
            float x_lo = fmaf((float)idx, H, X0);    // exact, matches xt[idx]
            float interp = fmaf(val - x_lo, seg.y, seg.x);
            r[k] = (val <  x_lo_bound) ? val
                 : (val >= x_hi_bound) ? 0.0f
                 : interp;
        }
        float4 o; o.x = r[0]; o.y = r[1]; o.z = r[2]; o.w = r[3];
        out4[base + j * THREADS] = o;
    }
}

// Tail kernel: scalar, handles [start, n) elements (not hit for this shape,
// but keeps the kernel correct for any n).
__global__ void logsig_pwl_tail(const float* __restrict__ vals,
                                const float* __restrict__ xt,
                                const float* __restrict__ yt,
                                float* __restrict__ out,
                                long long start, long long n)
{
    long long i = start + (long long)blockIdx.x * blockDim.x + threadIdx.x;
    if (i >= n) return;
    float x0 = xt[0];
    float xK = xt[NBP - 1];
    float val = vals[i];
    int idx = (int)fmaf(val, 3.2f, 32.0f);
    idx = max(0, min(idx, NSEG - 1));
    float x_lo = xt[idx];
    float y_lo = yt[idx];
    float slope = (yt[idx + 1] - y_lo) / (xt[idx + 1] - x_lo);
    float interp = fmaf(val - x_lo, slope, y_lo);
    out[i] = (val < x0) ? val : (val >= xK) ? 0.0f : interp;
}

extern "C" void kernel_launch(void* const* d_in, const int* in_sizes, int n_in,
                              void* d_out, int out_size)
{
    const float* vals = (const float*)d_in[0];
    const float* xt   = (const float*)d_in[1];
    const float* yt   = (const float*)d_in[2];
    float* out        = (float*)d_out;

    long long n  = (long long)in_sizes[0];
    long long n4 = n / 4;

    long long fullBlocks = n4 / TILE_F4;
    long long covered    = fullBlocks * TILE_F4 * 4;   // elements by main kernel

    if (fullBlocks > 0) {
        logsig_pwl_kernel<<<(unsigned)fullBlocks, THREADS>>>(
            (const float4*)vals, xt, yt, (float4*)out);
    }
    if (covered < n) {
        long long rem = n - covered;
        int tblocks = (int)((rem + 255) / 256);
        logsig_pwl_tail<<<tblocks, 256>>>(vals, xt, yt, out, covered, n);
    }
}